// round 11
// baseline (speedup 1.0000x reference)
#include <cuda_runtime.h>
#include <math.h>

// ---------------- problem constants ----------------
#define NRBF     32
#define CUTOFF_F 5.0f
#define GAMMA_F  40.96f                 // (NRBF/CUTOFF)^2
#define STEP_F   (5.0f / 31.0f)
#define INVSTEP_F (31.0f / 5.0f)
#define PI_F     3.14159265358979323846f
#define MAXN     50000

// scratch accumulator [N,16,8]
__device__ float g_agg[(size_t)MAXN * 128];

// ---------------- f32x2 packed helpers (FFMA2 path, sm_100+) ----------------
__device__ __forceinline__ unsigned long long pack2(float lo, float hi) {
    unsigned long long r;
    asm("mov.b64 %0, {%1, %2};" : "=l"(r) : "f"(lo), "f"(hi));
    return r;
}
__device__ __forceinline__ void unpack2(unsigned long long v, float& lo, float& hi) {
    asm("mov.b64 {%0, %1}, %2;" : "=f"(lo), "=f"(hi) : "l"(v));
}
__device__ __forceinline__ void fma2(unsigned long long& d,
                                     unsigned long long a,
                                     unsigned long long b) {
    asm("fma.rn.f32x2 %0, %1, %2, %3;" : "=l"(d) : "l"(a), "l"(b), "l"(d));
}

// ---------------- fused filter + edge pass (unchanged) ----------------
__global__ void __launch_bounds__(256) edge_fused_kernel(
    const float* __restrict__ h,
    const float* __restrict__ pos,
    const int*   __restrict__ ei,
    const float* __restrict__ Wrbf,   // [32,16] row-major
    int E)
{
    __shared__ float sW[NRBF * 16];
    int t = threadIdx.x;
    sW[t]       = Wrbf[t];
    sW[t + 256] = Wrbf[t + 256];
    __syncthreads();

    const unsigned FULL = 0xFFFFFFFFu;
    int lane  = t & 31;
    int hlane = t & 15;
    unsigned gbase = (unsigned)(t & 16);
    unsigned gmask = 0xFFFFu << gbase;
    int half  = (t >> 4) & 1;

    int e = (blockIdx.x * 8 + (t >> 5)) * 32 + lane;
    bool valid = e < E;
    int src = 0, dst = 0;
    if (valid) { src = __ldg(ei + e); dst = __ldg(ei + E + e); }

    float rx = 0.f, ry = 0.f, rz = 0.f;
    if (valid) {
        rx = __ldg(pos + dst * 3 + 0) - __ldg(pos + src * 3 + 0);
        ry = __ldg(pos + dst * 3 + 1) - __ldg(pos + src * 3 + 1);
        rz = __ldg(pos + dst * 3 + 2) - __ldg(pos + src * 3 + 2);
    }
    float d = sqrtf(rx * rx + ry * ry + rz * rz + 1e-12f);
    bool live = valid && (d < CUTOFF_F);
    float inv = 1.0f / d;
    float ux = rx * inv, uy = ry * inv, uz = rz * inv;

    unsigned mask = __ballot_sync(FULL, live);

    while (mask) {
        int s0 = __ffs(mask) - 1;
        unsigned m2 = mask & (mask - 1);
        int s1 = m2 ? (__ffs(m2) - 1) : 32;
        mask = m2 ? (m2 & (m2 - 1)) : 0u;

        int sl = half ? s1 : s0;
        bool act = sl < 32;
        int srcl = sl & 31;

        int   ssrc = __shfl_sync(FULL, src, srcl);
        int   sdst = __shfl_sync(FULL, dst, srcl);
        float sux  = __shfl_sync(FULL, ux,  srcl);
        float suy  = __shfl_sync(FULL, uy,  srcl);
        float suz  = __shfl_sync(FULL, uz,  srcl);
        float sd   = __shfl_sync(FULL, d,   srcl);

        if (act) {
            const float4* hp = (const float4*)(h + (size_t)ssrc * 128 + hlane * 8);
            float4 A0 = __ldg(hp), A1 = __ldg(hp + 1);

            int k0 = __float2int_rn(sd * INVSTEP_F);
            k0 = min(max(k0, 0), 31);
            float r = 0.f;
            {
                int k = k0 + hlane - 4;
                if (hlane < 9 && k >= 0 && k <= 31) {
                    float dd = sd - (float)k * STEP_F;
                    r = __expf(-GAMMA_F * dd * dd);
                }
            }
            float w = 0.f;
            #pragma unroll
            for (int m = 0; m < 9; m++) {
                float rm = __shfl_sync(gmask, r, gbase + m, 32);
                int km = k0 + m - 4;
                int kc = min(max(km, 0), 31);
                w += rm * sW[kc * 16 + hlane];
            }
            w *= 0.5f * (__cosf((PI_F / CUTOFF_F) * sd) + 1.0f);

            float wx = w * sux, wy = w * suy, wz = w * suz;

            float a0 = A0.x, a1 = A0.y, a2 = A0.z, a3 = A0.w;
            float a4 = A1.x, a5 = A1.y, a6 = A1.z, a7 = A1.w;

            float m0 = a1 * wx + a2 * wy + a3 * wz;
            float m1 = a0 * wx + a4 * wy + a5 * wz;
            float m2v= a0 * wy + a6 * wz - a4 * wx;
            float m3 = a0 * wz - a5 * wx - a6 * wy;
            float m4 = a1 * wy + a7 * wz - a2 * wx;
            float m5 = a1 * wz - a3 * wx - a7 * wy;
            float m6 = a7 * wx - a3 * wy + a2 * wz;
            float m7 = a6 * wx - a5 * wy + a4 * wz;

            float* p = g_agg + (size_t)sdst * 128 + hlane * 8;
            asm volatile("red.global.add.v4.f32 [%0], {%1,%2,%3,%4};"
                         :: "l"(p), "f"(m0), "f"(m1), "f"(m2v), "f"(m3) : "memory");
            asm volatile("red.global.add.v4.f32 [%0], {%1,%2,%3,%4};"
                         :: "l"(p + 4), "f"(m4), "f"(m5), "f"(m6), "f"(m7) : "memory");
        }
    }
}

// ---------------- node pass: 16 nodes/block (128 thr), G=2, no h staging ----
// thread = (nl = t>>3, oo = t&7); outputs oo and oo+8.
// agg tile staged in smem (padded); h read directly from global — the 8
// threads of a node issue identical addresses, dedup'd by the L1 coalescer,
// and h is L2-hot from the edge pass.
#define NODE_STRIDE 136   // floats; 544B: 16B-aligned, +8 banks between nodes

__global__ void __launch_bounds__(128) node_kernel(
    const float* __restrict__ h,
    const float* __restrict__ Wout,   // [16,16] row-major W[c*16+o]
    const float* __restrict__ Wsgp,
    float* __restrict__ res,
    int N)
{
    __shared__ float s_a[16 * NODE_STRIDE];   // 8.7 KB
    __shared__ float s_wo[256];
    __shared__ float s_wq[256];

    int t = threadIdx.x;
    s_wo[t] = Wout[t];  s_wo[t + 128] = Wout[t + 128];
    s_wq[t] = Wsgp[t];  s_wq[t + 128] = Wsgp[t + 128];

    int basen = blockIdx.x * 16;
    int nv4 = min(16, N - basen) * 32;   // float4s of agg to stage

    const float4* ga = (const float4*)(g_agg + (size_t)basen * 128);
    #pragma unroll
    for (int k = 0; k < 4; k++) {
        int idx = t + k * 128;
        if (idx < nv4) {
            int node  = idx >> 5;
            int inner = idx & 31;
            *(float4*)&s_a[node * NODE_STRIDE + inner * 4] = __ldg(ga + idx);
        }
    }
    __syncthreads();

    int nl = t >> 3;
    int node = basen + nl;
    if (node >= N) return;
    int oo = t & 7;                      // outputs oo and oo+8

    unsigned long long aA[4], aB[4], qA[4], qB[4];
    unsigned long long z = pack2(0.f, 0.f);
    #pragma unroll
    for (int i = 0; i < 4; i++) { aA[i] = z; aB[i] = z; qA[i] = z; qB[i] = z; }

    const float*  A = s_a + nl * NODE_STRIDE;
    const float4* H = (const float4*)(h + (size_t)node * 128);

    #pragma unroll
    for (int c = 0; c < 16; c++) {
        float woa = s_wo[c * 16 + oo];
        float wob = s_wo[c * 16 + oo + 8];
        float wqa = s_wq[c * 16 + oo];
        float wqb = s_wq[c * 16 + oo + 8];
        unsigned long long woa2 = pack2(woa, woa);
        unsigned long long wob2 = pack2(wob, wob);
        unsigned long long wqa2 = pack2(wqa, wqa);
        unsigned long long wqb2 = pack2(wqb, wqb);

        const float4* x = (const float4*)(A + c * 8);
        float4 x0 = x[0], x1 = x[1];
        float4 y0 = __ldg(H + c * 2), y1 = __ldg(H + c * 2 + 1);

        unsigned long long p0 = pack2(x0.x, x0.y), p1 = pack2(x0.z, x0.w);
        unsigned long long p2 = pack2(x1.x, x1.y), p3 = pack2(x1.z, x1.w);
        unsigned long long r0 = pack2(y0.x, y0.y), r1 = pack2(y0.z, y0.w);
        unsigned long long r2 = pack2(y1.x, y1.y), r3 = pack2(y1.z, y1.w);

        fma2(aA[0], p0, woa2); fma2(aA[1], p1, woa2);
        fma2(aA[2], p2, woa2); fma2(aA[3], p3, woa2);
        fma2(aB[0], p0, wob2); fma2(aB[1], p1, wob2);
        fma2(aB[2], p2, wob2); fma2(aB[3], p3, wob2);
        fma2(qA[0], r0, wqa2); fma2(qA[1], r1, wqa2);
        fma2(qA[2], r2, wqa2); fma2(qA[3], r3, wqa2);
        fma2(qB[0], r0, wqb2); fma2(qB[1], r1, wqb2);
        fma2(qB[2], r2, wqb2); fma2(qB[3], r3, wqb2);
    }

    float* outbase = res + (size_t)node * 128;

    #pragma unroll
    for (int half = 0; half < 2; half++) {
        unsigned long long* a2 = half ? aB : aA;
        unsigned long long* q2 = half ? qB : qA;
        float a[8], q[8];
        #pragma unroll
        for (int i = 0; i < 4; i++) {
            unpack2(a2[i], a[2 * i], a[2 * i + 1]);
            unpack2(q2[i], q[2 * i], q[2 * i + 1]);
        }

        float g0 = a[0]*q[0] + a[1]*q[1] + a[2]*q[2] + a[3]*q[3] - a[4]*q[4] - a[5]*q[5] - a[6]*q[6] - a[7]*q[7];
        float g1 = a[0]*q[1] + a[1]*q[0] - a[2]*q[4] - a[3]*q[5] + a[4]*q[2] + a[5]*q[3] - a[6]*q[7] - a[7]*q[6];
        float g2 = a[0]*q[2] + a[1]*q[4] + a[2]*q[0] - a[3]*q[6] - a[4]*q[1] + a[5]*q[7] + a[6]*q[3] + a[7]*q[5];
        float g3 = a[0]*q[3] + a[1]*q[5] + a[2]*q[6] + a[3]*q[0] - a[4]*q[7] - a[5]*q[1] - a[6]*q[2] - a[7]*q[4];
        float g4 = a[0]*q[4] + a[1]*q[2] - a[2]*q[1] + a[3]*q[7] + a[4]*q[0] - a[5]*q[6] + a[6]*q[5] + a[7]*q[3];
        float g5 = a[0]*q[5] + a[1]*q[3] - a[2]*q[7] - a[3]*q[1] + a[4]*q[6] + a[5]*q[0] - a[6]*q[4] - a[7]*q[2];
        float g6 = a[0]*q[6] + a[1]*q[7] + a[2]*q[3] - a[3]*q[2] - a[4]*q[5] + a[5]*q[4] + a[6]*q[0] + a[7]*q[1];
        float g7 = a[0]*q[7] + a[1]*q[6] - a[2]*q[5] + a[3]*q[4] + a[4]*q[3] - a[5]*q[2] + a[6]*q[1] + a[7]*q[0];

        float* op = outbase + (oo + half * 8) * 8;
        ((float4*)op)[0] = make_float4(a[0] + g0, a[1] + g1, a[2] + g2, a[3] + g3);
        ((float4*)op)[1] = make_float4(a[4] + g4, a[5] + g5, a[6] + g6, a[7] + g7);
    }
}

// ---------------- launch ----------------
extern "C" void kernel_launch(void* const* d_in, const int* in_sizes, int n_in,
                              void* d_out, int out_size)
{
    const float* h    = (const float*)d_in[0];
    const float* pos  = (const float*)d_in[1];
    const int*   ei   = (const int*)  d_in[2];
    const float* Wrbf = (const float*)d_in[3];
    const float* Wout = (const float*)d_in[4];
    const float* Wsgp = (const float*)d_in[5];
    float* out = (float*)d_out;

    int N = in_sizes[0] / 128;
    int E = in_sizes[2] / 2;
    if (N > MAXN) N = MAXN;

    void* agg_ptr = nullptr;
    cudaGetSymbolAddress(&agg_ptr, g_agg);
    cudaMemsetAsync(agg_ptr, 0, (size_t)N * 128 * sizeof(float), 0);

    int blocks = (E + 255) / 256;
    edge_fused_kernel<<<blocks, 256>>>(h, pos, ei, Wrbf, E);
    node_kernel<<<(N + 15) / 16, 128>>>(h, Wout, Wsgp, out, N);
}

// round 12
// speedup vs baseline: 1.1718x; 1.1718x over previous
#include <cuda_runtime.h>
#include <math.h>

// ---------------- problem constants ----------------
#define NRBF     32
#define CUTOFF_F 5.0f
#define GAMMA_F  40.96f                 // (NRBF/CUTOFF)^2
#define STEP_F   (5.0f / 31.0f)
#define INVSTEP_F (31.0f / 5.0f)
#define PI_F     3.14159265358979323846f
#define MAXN     50000

// scratch accumulator [N,16,8]
__device__ float g_agg[(size_t)MAXN * 128];

// ---------------- f32x2 packed helpers (FFMA2 path, sm_100+) ----------------
__device__ __forceinline__ unsigned long long pack2(float lo, float hi) {
    unsigned long long r;
    asm("mov.b64 %0, {%1, %2};" : "=l"(r) : "f"(lo), "f"(hi));
    return r;
}
__device__ __forceinline__ void unpack2(unsigned long long v, float& lo, float& hi) {
    asm("mov.b64 {%0, %1}, %2;" : "=f"(lo), "=f"(hi) : "l"(v));
}
__device__ __forceinline__ void fma2(unsigned long long& d,
                                     unsigned long long a,
                                     unsigned long long b) {
    asm("fma.rn.f32x2 %0, %1, %2, %3;" : "=l"(d) : "l"(a), "l"(b), "l"(d));
}

// ---------------- fused filter + edge pass: 64 edges/warp, batch-2 filter ----
__global__ void __launch_bounds__(256) edge_fused_kernel(
    const float* __restrict__ h,
    const float* __restrict__ pos,
    const int*   __restrict__ ei,
    const float* __restrict__ Wrbf,   // [32,16] row-major
    int E)
{
    __shared__ float sW[NRBF * 16];
    int t = threadIdx.x;
    sW[t]       = Wrbf[t];
    sW[t + 256] = Wrbf[t + 256];
    __syncthreads();

    const unsigned FULL = 0xFFFFFFFFu;
    int lane  = t & 31;
    int hlane = t & 15;
    unsigned gbase = (unsigned)(t & 16);
    unsigned gmask = 0xFFFFu << gbase;
    int half  = (t >> 4) & 1;

    // ---- filter phase: 2 edges per lane, gathers issued up front ----
    int e0 = (blockIdx.x * 8 + (t >> 5)) * 64 + lane;   // round 0 edge
    int e1 = e0 + 32;                                    // round 1 edge
    bool v0 = e0 < E, v1 = e1 < E;

    int src0 = 0, dst0 = 0, src1 = 0, dst1 = 0;
    if (v0) { src0 = __ldg(ei + e0); dst0 = __ldg(ei + E + e0); }
    if (v1) { src1 = __ldg(ei + e1); dst1 = __ldg(ei + E + e1); }

    // 12 independent pos gathers
    float s0x = 0.f, s0y = 0.f, s0z = 0.f, d0x = 0.f, d0y = 0.f, d0z = 0.f;
    float s1x = 0.f, s1y = 0.f, s1z = 0.f, d1x = 0.f, d1y = 0.f, d1z = 0.f;
    if (v0) {
        s0x = __ldg(pos + src0 * 3 + 0); s0y = __ldg(pos + src0 * 3 + 1); s0z = __ldg(pos + src0 * 3 + 2);
        d0x = __ldg(pos + dst0 * 3 + 0); d0y = __ldg(pos + dst0 * 3 + 1); d0z = __ldg(pos + dst0 * 3 + 2);
    }
    if (v1) {
        s1x = __ldg(pos + src1 * 3 + 0); s1y = __ldg(pos + src1 * 3 + 1); s1z = __ldg(pos + src1 * 3 + 2);
        d1x = __ldg(pos + dst1 * 3 + 0); d1y = __ldg(pos + dst1 * 3 + 1); d1z = __ldg(pos + dst1 * 3 + 2);
    }

    float r0x = d0x - s0x, r0y = d0y - s0y, r0z = d0z - s0z;
    float r1x = d1x - s1x, r1y = d1y - s1y, r1z = d1z - s1z;
    float dA = sqrtf(r0x * r0x + r0y * r0y + r0z * r0z + 1e-12f);
    float dB = sqrtf(r1x * r1x + r1y * r1y + r1z * r1z + 1e-12f);
    bool live0 = v0 && (dA < CUTOFF_F);
    bool live1 = v1 && (dB < CUTOFF_F);
    float invA = 1.0f / dA, invB = 1.0f / dB;
    float u0x = r0x * invA, u0y = r0y * invA, u0z = r0z * invA;
    float u1x = r1x * invB, u1y = r1y * invB, u1z = r1z * invB;

    unsigned mask0 = __ballot_sync(FULL, live0);
    unsigned mask1 = __ballot_sync(FULL, live1);

    // ---- heavy phase: two rounds, 2 survivors per iteration ----
    #pragma unroll
    for (int rnd = 0; rnd < 2; rnd++) {
        unsigned mask = rnd ? mask1 : mask0;
        int   csrc = rnd ? src1 : src0;
        int   cdst = rnd ? dst1 : dst0;
        float cux  = rnd ? u1x : u0x;
        float cuy  = rnd ? u1y : u0y;
        float cuz  = rnd ? u1z : u0z;
        float cd   = rnd ? dB  : dA;

        while (mask) {
            int s0 = __ffs(mask) - 1;
            unsigned m2 = mask & (mask - 1);
            int s1 = m2 ? (__ffs(m2) - 1) : 32;
            mask = m2 ? (m2 & (m2 - 1)) : 0u;

            int sl = half ? s1 : s0;
            bool act = sl < 32;
            int srcl = sl & 31;

            int   ssrc = __shfl_sync(FULL, csrc, srcl);
            int   sdst = __shfl_sync(FULL, cdst, srcl);
            float sux  = __shfl_sync(FULL, cux,  srcl);
            float suy  = __shfl_sync(FULL, cuy,  srcl);
            float suz  = __shfl_sync(FULL, cuz,  srcl);
            float sd   = __shfl_sync(FULL, cd,   srcl);

            if (act) {
                const float4* hp = (const float4*)(h + (size_t)ssrc * 128 + hlane * 8);
                float4 A0 = __ldg(hp), A1 = __ldg(hp + 1);

                int k0 = __float2int_rn(sd * INVSTEP_F);
                k0 = min(max(k0, 0), 31);
                float r = 0.f;
                {
                    int k = k0 + hlane - 4;
                    if (hlane < 9 && k >= 0 && k <= 31) {
                        float dd = sd - (float)k * STEP_F;
                        r = __expf(-GAMMA_F * dd * dd);
                    }
                }
                float w = 0.f;
                #pragma unroll
                for (int m = 0; m < 9; m++) {
                    float rm = __shfl_sync(gmask, r, gbase + m, 32);
                    int km = k0 + m - 4;
                    int kc = min(max(km, 0), 31);
                    w += rm * sW[kc * 16 + hlane];
                }
                w *= 0.5f * (__cosf((PI_F / CUTOFF_F) * sd) + 1.0f);

                float wx = w * sux, wy = w * suy, wz = w * suz;

                float a0 = A0.x, a1 = A0.y, a2 = A0.z, a3 = A0.w;
                float a4 = A1.x, a5 = A1.y, a6 = A1.z, a7 = A1.w;

                float m0 = a1 * wx + a2 * wy + a3 * wz;
                float m1 = a0 * wx + a4 * wy + a5 * wz;
                float m2v= a0 * wy + a6 * wz - a4 * wx;
                float m3 = a0 * wz - a5 * wx - a6 * wy;
                float m4 = a1 * wy + a7 * wz - a2 * wx;
                float m5 = a1 * wz - a3 * wx - a7 * wy;
                float m6 = a7 * wx - a3 * wy + a2 * wz;
                float m7 = a6 * wx - a5 * wy + a4 * wz;

                float* p = g_agg + (size_t)sdst * 128 + hlane * 8;
                asm volatile("red.global.add.v4.f32 [%0], {%1,%2,%3,%4};"
                             :: "l"(p), "f"(m0), "f"(m1), "f"(m2v), "f"(m3) : "memory");
                asm volatile("red.global.add.v4.f32 [%0], {%1,%2,%3,%4};"
                             :: "l"(p + 4), "f"(m4), "f"(m5), "f"(m6), "f"(m7) : "memory");
            }
        }
    }
}

// ---------------- node pass: R8 configuration (best measured: 19.2us) ----------
// 32 nodes/block, 128 threads, 4 output channels/thread.
#define NODE_STRIDE 136   // floats; 544B: 16B-aligned, +8 banks between nodes

__global__ void __launch_bounds__(128, 4) node_kernel(
    const float* __restrict__ h,
    const float* __restrict__ Wout,   // [16,16] row-major W[c*16+o]
    const float* __restrict__ Wsgp,
    float* __restrict__ res,
    int N)
{
    __shared__ float s_a[32 * NODE_STRIDE];
    __shared__ float s_h[32 * NODE_STRIDE];
    __shared__ float4 s_wo4[64];   // [c][oo] -> (W[c][oo],W[c][oo+4],W[c][oo+8],W[c][oo+12])
    __shared__ float4 s_wq4[64];

    int t = threadIdx.x;
    if (t < 64) {
        int c = t >> 2, oo = t & 3;
        const float* wr = Wout + c * 16 + oo;
        const float* qr = Wsgp + c * 16 + oo;
        s_wo4[t] = make_float4(wr[0], wr[4], wr[8], wr[12]);
        s_wq4[t] = make_float4(qr[0], qr[4], qr[8], qr[12]);
    }

    int basen = blockIdx.x * 32;
    int nv4 = min(32, N - basen) * 32;   // float4s per array

    const float4* ga = (const float4*)(g_agg + (size_t)basen * 128);
    const float4* gh = (const float4*)(h     + (size_t)basen * 128);
    #pragma unroll
    for (int k = 0; k < 8; k++) {
        int idx = t + k * 128;
        if (idx < nv4) {
            int node  = idx >> 5;
            int inner = idx & 31;
            float4 va = __ldg(ga + idx);
            float4 vh = __ldg(gh + idx);
            *(float4*)&s_a[node * NODE_STRIDE + inner * 4] = va;
            *(float4*)&s_h[node * NODE_STRIDE + inner * 4] = vh;
        }
    }
    __syncthreads();

    int nl = t >> 2;
    int node = basen + nl;
    if (node >= N) return;
    int oo = t & 3;

    unsigned long long aacc[4][4], qacc[4][4];
    unsigned long long z = pack2(0.f, 0.f);
    #pragma unroll
    for (int j = 0; j < 4; j++)
        #pragma unroll
        for (int i = 0; i < 4; i++) { aacc[j][i] = z; qacc[j][i] = z; }

    const float* A = s_a + nl * NODE_STRIDE;
    const float* H = s_h + nl * NODE_STRIDE;

    #pragma unroll
    for (int c = 0; c < 16; c++) {
        float4 w_o = s_wo4[c * 4 + oo];
        float4 w_q = s_wq4[c * 4 + oo];
        const float4* x = (const float4*)(A + c * 8);
        const float4* y = (const float4*)(H + c * 8);
        float4 x0 = x[0], x1 = x[1];
        float4 y0 = y[0], y1 = y[1];
        unsigned long long p0 = pack2(x0.x, x0.y), p1 = pack2(x0.z, x0.w);
        unsigned long long p2 = pack2(x1.x, x1.y), p3 = pack2(x1.z, x1.w);
        unsigned long long r0 = pack2(y0.x, y0.y), r1 = pack2(y0.z, y0.w);
        unsigned long long r2 = pack2(y1.x, y1.y), r3 = pack2(y1.z, y1.w);

        float wos[4] = {w_o.x, w_o.y, w_o.z, w_o.w};
        float wqs[4] = {w_q.x, w_q.y, w_q.z, w_q.w};
        #pragma unroll
        for (int j = 0; j < 4; j++) {
            unsigned long long wo2 = pack2(wos[j], wos[j]);
            unsigned long long wq2 = pack2(wqs[j], wqs[j]);
            fma2(aacc[j][0], p0, wo2); fma2(aacc[j][1], p1, wo2);
            fma2(aacc[j][2], p2, wo2); fma2(aacc[j][3], p3, wo2);
            fma2(qacc[j][0], r0, wq2); fma2(qacc[j][1], r1, wq2);
            fma2(qacc[j][2], r2, wq2); fma2(qacc[j][3], r3, wq2);
        }
    }

    float* outbase = res + (size_t)node * 128;

    #pragma unroll
    for (int j = 0; j < 4; j++) {
        float a[8], q[8];
        #pragma unroll
        for (int i = 0; i < 4; i++) {
            unpack2(aacc[j][i], a[2 * i], a[2 * i + 1]);
            unpack2(qacc[j][i], q[2 * i], q[2 * i + 1]);
        }

        float g0 = a[0]*q[0] + a[1]*q[1] + a[2]*q[2] + a[3]*q[3] - a[4]*q[4] - a[5]*q[5] - a[6]*q[6] - a[7]*q[7];
        float g1 = a[0]*q[1] + a[1]*q[0] - a[2]*q[4] - a[3]*q[5] + a[4]*q[2] + a[5]*q[3] - a[6]*q[7] - a[7]*q[6];
        float g2 = a[0]*q[2] + a[1]*q[4] + a[2]*q[0] - a[3]*q[6] - a[4]*q[1] + a[5]*q[7] + a[6]*q[3] + a[7]*q[5];
        float g3 = a[0]*q[3] + a[1]*q[5] + a[2]*q[6] + a[3]*q[0] - a[4]*q[7] - a[5]*q[1] - a[6]*q[2] - a[7]*q[4];
        float g4 = a[0]*q[4] + a[1]*q[2] - a[2]*q[1] + a[3]*q[7] + a[4]*q[0] - a[5]*q[6] + a[6]*q[5] + a[7]*q[3];
        float g5 = a[0]*q[5] + a[1]*q[3] - a[2]*q[7] - a[3]*q[1] + a[4]*q[6] + a[5]*q[0] - a[6]*q[4] - a[7]*q[2];
        float g6 = a[0]*q[6] + a[1]*q[7] + a[2]*q[3] - a[3]*q[2] - a[4]*q[5] + a[5]*q[4] + a[6]*q[0] + a[7]*q[1];
        float g7 = a[0]*q[7] + a[1]*q[6] - a[2]*q[5] + a[3]*q[4] + a[4]*q[3] - a[5]*q[2] + a[6]*q[1] + a[7]*q[0];

        float* op = outbase + (oo + j * 4) * 8;
        ((float4*)op)[0] = make_float4(a[0] + g0, a[1] + g1, a[2] + g2, a[3] + g3);
        ((float4*)op)[1] = make_float4(a[4] + g4, a[5] + g5, a[6] + g6, a[7] + g7);
    }
}

// ---------------- launch ----------------
extern "C" void kernel_launch(void* const* d_in, const int* in_sizes, int n_in,
                              void* d_out, int out_size)
{
    const float* h    = (const float*)d_in[0];
    const float* pos  = (const float*)d_in[1];
    const int*   ei   = (const int*)  d_in[2];
    const float* Wrbf = (const float*)d_in[3];
    const float* Wout = (const float*)d_in[4];
    const float* Wsgp = (const float*)d_in[5];
    float* out = (float*)d_out;

    int N = in_sizes[0] / 128;
    int E = in_sizes[2] / 2;
    if (N > MAXN) N = MAXN;

    void* agg_ptr = nullptr;
    cudaGetSymbolAddress(&agg_ptr, g_agg);
    cudaMemsetAsync(agg_ptr, 0, (size_t)N * 128 * sizeof(float), 0);

    // 8 warps/block, 64 edges/warp => 512 edges per block
    int blocks = (E + 511) / 512;
    edge_fused_kernel<<<blocks, 256>>>(h, pos, ei, Wrbf, E);
    node_kernel<<<(N + 31) / 32, 128>>>(h, Wout, Wsgp, out, N);
}

// round 14
// speedup vs baseline: 1.2098x; 1.0324x over previous
#include <cuda_runtime.h>
#include <math.h>

// ---------------- problem constants ----------------
#define NRBF     32
#define CUTOFF_F 5.0f
#define GAMMA_F  40.96f                 // (32/5)^2
#define STEP_F   (5.0f / 31.0f)
#define INVSTEP_F (31.0f / 5.0f)
#define PI_F     3.14159265358979323846f
#define MAXN     50000

// RBF closed-form constants: gs2 = gamma*step^2 = 1024/961 = 1.0655567
// E_m = exp(-m^2 * gs2)  (cumulative, NOT per-step ratios)
#define C2GS     13.2129032f            // 2*gamma*step = 2048/155
#define E1C      0.3445350f             // exp(-1*gs2)
#define E2C      0.0140906f             // exp(-4*gs2)
#define E3C      6.8410e-5f             // exp(-9*gs2)
#define E4C      3.9424e-8f             // exp(-16*gs2)

// scratch accumulator [N,16,8]
__device__ float g_agg[(size_t)MAXN * 128];

// ---------------- f32x2 packed helpers (FFMA2 path, sm_100+) ----------------
__device__ __forceinline__ unsigned long long pack2(float lo, float hi) {
    unsigned long long r;
    asm("mov.b64 %0, {%1, %2};" : "=l"(r) : "f"(lo), "f"(hi));
    return r;
}
__device__ __forceinline__ void unpack2(unsigned long long v, float& lo, float& hi) {
    asm("mov.b64 {%0, %1}, %2;" : "=f"(lo), "=f"(hi) : "l"(v));
}
__device__ __forceinline__ void fma2(unsigned long long& d,
                                     unsigned long long a,
                                     unsigned long long b) {
    asm("fma.rn.f32x2 %0, %1, %2, %3;" : "=l"(d) : "l"(a), "l"(b), "l"(d));
}

// ---------------- fused filter + edge pass ----------------
// One warp takes 32 raw edges; survivors processed 2 per iteration
// (16 lanes each). RBF weight via closed form: r_m = base * up^m * E_m.
__global__ void __launch_bounds__(256) edge_fused_kernel(
    const float* __restrict__ h,
    const float* __restrict__ pos,
    const int*   __restrict__ ei,
    const float* __restrict__ Wrbf,   // [32,16] row-major
    int E)
{
    __shared__ float sW[NRBF * 16];
    int t = threadIdx.x;
    sW[t]       = Wrbf[t];
    sW[t + 256] = Wrbf[t + 256];
    __syncthreads();

    const unsigned FULL = 0xFFFFFFFFu;
    int lane  = t & 31;
    int hlane = t & 15;
    int half  = (t >> 4) & 1;

    // ---- filter phase: 1 edge per lane ----
    int e = (blockIdx.x * 8 + (t >> 5)) * 32 + lane;
    bool valid = e < E;
    int src = 0, dst = 0;
    if (valid) { src = __ldg(ei + e); dst = __ldg(ei + E + e); }

    float rx = 0.f, ry = 0.f, rz = 0.f;
    if (valid) {
        rx = __ldg(pos + dst * 3 + 0) - __ldg(pos + src * 3 + 0);
        ry = __ldg(pos + dst * 3 + 1) - __ldg(pos + src * 3 + 1);
        rz = __ldg(pos + dst * 3 + 2) - __ldg(pos + src * 3 + 2);
    }
    float d = sqrtf(rx * rx + ry * ry + rz * rz + 1e-12f);
    bool live = valid && (d < CUTOFF_F);
    float inv = 1.0f / d;
    float ux = rx * inv, uy = ry * inv, uz = rz * inv;

    unsigned mask = __ballot_sync(FULL, live);

    // ---- heavy phase ----
    while (mask) {
        int s0 = __ffs(mask) - 1;
        unsigned m2 = mask & (mask - 1);
        int s1 = m2 ? (__ffs(m2) - 1) : 32;
        mask = m2 ? (m2 & (m2 - 1)) : 0u;

        int sl = half ? s1 : s0;
        bool act = sl < 32;
        int srcl = sl & 31;

        int   ssrc = __shfl_sync(FULL, src, srcl);
        int   sdst = __shfl_sync(FULL, dst, srcl);
        float sux  = __shfl_sync(FULL, ux,  srcl);
        float suy  = __shfl_sync(FULL, uy,  srcl);
        float suz  = __shfl_sync(FULL, uz,  srcl);
        float sd   = __shfl_sync(FULL, d,   srcl);

        if (act) {
            // issue h-gather first; latency hides under the RBF math below
            const float4* hp = (const float4*)(h + (size_t)ssrc * 128 + hlane * 8);
            float4 A0 = __ldg(hp), A1 = __ldg(hp + 1);

            // ---- RBF weight: closed form, no shuffles ----
            // r_{k0+m} = exp(-g*(delta - m*step)^2) = base * up^m * E_m
            int k0 = __float2int_rn(sd * INVSTEP_F);
            k0 = min(max(k0, 0), 31);
            float delta = sd - (float)k0 * STEP_F;

            float env  = 0.5f * (__cosf((PI_F / CUTOFF_F) * sd) + 1.0f);
            float base = __expf(-GAMMA_F * delta * delta) * env;
            float up   = __expf( C2GS * delta);
            float un   = 1.0f / up;

            const float* Wrow = sW + hlane;   // column c = hlane, stride 16
            float w = base * Wrow[k0 * 16];

            float t1 = base * up;
            float t2 = t1 * up, t3 = t2 * up, t4 = t3 * up;
            if (k0 + 1 <= 31) w += t1 * E1C * Wrow[(k0 + 1) * 16];
            if (k0 + 2 <= 31) w += t2 * E2C * Wrow[(k0 + 2) * 16];
            if (k0 + 3 <= 31) w += t3 * E3C * Wrow[(k0 + 3) * 16];
            if (k0 + 4 <= 31) w += t4 * E4C * Wrow[(k0 + 4) * 16];
            float n1 = base * un;
            float n2 = n1 * un, n3 = n2 * un, n4 = n3 * un;
            if (k0 - 1 >= 0) w += n1 * E1C * Wrow[(k0 - 1) * 16];
            if (k0 - 2 >= 0) w += n2 * E2C * Wrow[(k0 - 2) * 16];
            if (k0 - 3 >= 0) w += n3 * E3C * Wrow[(k0 - 3) * 16];
            if (k0 - 4 >= 0) w += n4 * E4C * Wrow[(k0 - 4) * 16];

            float wx = w * sux, wy = w * suy, wz = w * suz;

            float a0 = A0.x, a1 = A0.y, a2 = A0.z, a3 = A0.w;
            float a4 = A1.x, a5 = A1.y, a6 = A1.z, a7 = A1.w;

            // gp(a, u)*w, Cl(3,0) shortlex
            float m0 = a1 * wx + a2 * wy + a3 * wz;
            float m1 = a0 * wx + a4 * wy + a5 * wz;
            float m2v= a0 * wy + a6 * wz - a4 * wx;
            float m3 = a0 * wz - a5 * wx - a6 * wy;
            float m4 = a1 * wy + a7 * wz - a2 * wx;
            float m5 = a1 * wz - a3 * wx - a7 * wy;
            float m6 = a7 * wx - a3 * wy + a2 * wz;
            float m7 = a6 * wx - a5 * wy + a4 * wz;

            float* p = g_agg + (size_t)sdst * 128 + hlane * 8;
            asm volatile("red.global.add.v4.f32 [%0], {%1,%2,%3,%4};"
                         :: "l"(p), "f"(m0), "f"(m1), "f"(m2v), "f"(m3) : "memory");
            asm volatile("red.global.add.v4.f32 [%0], {%1,%2,%3,%4};"
                         :: "l"(p + 4), "f"(m4), "f"(m5), "f"(m6), "f"(m7) : "memory");
        }
    }
}

// ---------------- node pass: R8 configuration (best measured) ----------------
// 32 nodes/block, 128 threads, 4 output channels/thread.
#define NODE_STRIDE 136   // floats; 544B: 16B-aligned, +8 banks between nodes

__global__ void __launch_bounds__(128, 4) node_kernel(
    const float* __restrict__ h,
    const float* __restrict__ Wout,   // [16,16] row-major W[c*16+o]
    const float* __restrict__ Wsgp,
    float* __restrict__ res,
    int N)
{
    __shared__ float s_a[32 * NODE_STRIDE];
    __shared__ float s_h[32 * NODE_STRIDE];
    __shared__ float4 s_wo4[64];   // [c][oo] -> (W[c][oo],W[c][oo+4],W[c][oo+8],W[c][oo+12])
    __shared__ float4 s_wq4[64];

    int t = threadIdx.x;
    if (t < 64) {
        int c = t >> 2, oo = t & 3;
        const float* wr = Wout + c * 16 + oo;
        const float* qr = Wsgp + c * 16 + oo;
        s_wo4[t] = make_float4(wr[0], wr[4], wr[8], wr[12]);
        s_wq4[t] = make_float4(qr[0], qr[4], qr[8], qr[12]);
    }

    int basen = blockIdx.x * 32;
    int nv4 = min(32, N - basen) * 32;   // float4s per array

    const float4* ga = (const float4*)(g_agg + (size_t)basen * 128);
    const float4* gh = (const float4*)(h     + (size_t)basen * 128);
    #pragma unroll
    for (int k = 0; k < 8; k++) {
        int idx = t + k * 128;
        if (idx < nv4) {
            int node  = idx >> 5;
            int inner = idx & 31;
            float4 va = __ldg(ga + idx);
            float4 vh = __ldg(gh + idx);
            *(float4*)&s_a[node * NODE_STRIDE + inner * 4] = va;
            *(float4*)&s_h[node * NODE_STRIDE + inner * 4] = vh;
        }
    }
    __syncthreads();

    int nl = t >> 2;
    int node = basen + nl;
    if (node >= N) return;
    int oo = t & 3;

    unsigned long long aacc[4][4], qacc[4][4];
    unsigned long long z = pack2(0.f, 0.f);
    #pragma unroll
    for (int j = 0; j < 4; j++)
        #pragma unroll
        for (int i = 0; i < 4; i++) { aacc[j][i] = z; qacc[j][i] = z; }

    const float* A = s_a + nl * NODE_STRIDE;
    const float* H = s_h + nl * NODE_STRIDE;

    #pragma unroll
    for (int c = 0; c < 16; c++) {
        float4 w_o = s_wo4[c * 4 + oo];
        float4 w_q = s_wq4[c * 4 + oo];
        const float4* x = (const float4*)(A + c * 8);
        const float4* y = (const float4*)(H + c * 8);
        float4 x0 = x[0], x1 = x[1];
        float4 y0 = y[0], y1 = y[1];
        unsigned long long p0 = pack2(x0.x, x0.y), p1 = pack2(x0.z, x0.w);
        unsigned long long p2 = pack2(x1.x, x1.y), p3 = pack2(x1.z, x1.w);
        unsigned long long r0 = pack2(y0.x, y0.y), r1 = pack2(y0.z, y0.w);
        unsigned long long r2 = pack2(y1.x, y1.y), r3 = pack2(y1.z, y1.w);

        float wos[4] = {w_o.x, w_o.y, w_o.z, w_o.w};
        float wqs[4] = {w_q.x, w_q.y, w_q.z, w_q.w};
        #pragma unroll
        for (int j = 0; j < 4; j++) {
            unsigned long long wo2 = pack2(wos[j], wos[j]);
            unsigned long long wq2 = pack2(wqs[j], wqs[j]);
            fma2(aacc[j][0], p0, wo2); fma2(aacc[j][1], p1, wo2);
            fma2(aacc[j][2], p2, wo2); fma2(aacc[j][3], p3, wo2);
            fma2(qacc[j][0], r0, wq2); fma2(qacc[j][1], r1, wq2);
            fma2(qacc[j][2], r2, wq2); fma2(qacc[j][3], r3, wq2);
        }
    }

    float* outbase = res + (size_t)node * 128;

    #pragma unroll
    for (int j = 0; j < 4; j++) {
        float a[8], q[8];
        #pragma unroll
        for (int i = 0; i < 4; i++) {
            unpack2(aacc[j][i], a[2 * i], a[2 * i + 1]);
            unpack2(qacc[j][i], q[2 * i], q[2 * i + 1]);
        }

        float g0 = a[0]*q[0] + a[1]*q[1] + a[2]*q[2] + a[3]*q[3] - a[4]*q[4] - a[5]*q[5] - a[6]*q[6] - a[7]*q[7];
        float g1 = a[0]*q[1] + a[1]*q[0] - a[2]*q[4] - a[3]*q[5] + a[4]*q[2] + a[5]*q[3] - a[6]*q[7] - a[7]*q[6];
        float g2 = a[0]*q[2] + a[1]*q[4] + a[2]*q[0] - a[3]*q[6] - a[4]*q[1] + a[5]*q[7] + a[6]*q[3] + a[7]*q[5];
        float g3 = a[0]*q[3] + a[1]*q[5] + a[2]*q[6] + a[3]*q[0] - a[4]*q[7] - a[5]*q[1] - a[6]*q[2] - a[7]*q[4];
        float g4 = a[0]*q[4] + a[1]*q[2] - a[2]*q[1] + a[3]*q[7] + a[4]*q[0] - a[5]*q[6] + a[6]*q[5] + a[7]*q[3];
        float g5 = a[0]*q[5] + a[1]*q[3] - a[2]*q[7] - a[3]*q[1] + a[4]*q[6] + a[5]*q[0] - a[6]*q[4] - a[7]*q[2];
        float g6 = a[0]*q[6] + a[1]*q[7] + a[2]*q[3] - a[3]*q[2] - a[4]*q[5] + a[5]*q[4] + a[6]*q[0] + a[7]*q[1];
        float g7 = a[0]*q[7] + a[1]*q[6] - a[2]*q[5] + a[3]*q[4] + a[4]*q[3] - a[5]*q[2] + a[6]*q[1] + a[7]*q[0];

        float* op = outbase + (oo + j * 4) * 8;
        ((float4*)op)[0] = make_float4(a[0] + g0, a[1] + g1, a[2] + g2, a[3] + g3);
        ((float4*)op)[1] = make_float4(a[4] + g4, a[5] + g5, a[6] + g6, a[7] + g7);
    }
}

// ---------------- launch ----------------
extern "C" void kernel_launch(void* const* d_in, const int* in_sizes, int n_in,
                              void* d_out, int out_size)
{
    const float* h    = (const float*)d_in[0];
    const float* pos  = (const float*)d_in[1];
    const int*   ei   = (const int*)  d_in[2];
    const float* Wrbf = (const float*)d_in[3];
    const float* Wout = (const float*)d_in[4];
    const float* Wsgp = (const float*)d_in[5];
    float* out = (float*)d_out;

    int N = in_sizes[0] / 128;
    int E = in_sizes[2] / 2;
    if (N > MAXN) N = MAXN;

    void* agg_ptr = nullptr;
    cudaGetSymbolAddress(&agg_ptr, g_agg);
    cudaMemsetAsync(agg_ptr, 0, (size_t)N * 128 * sizeof(float), 0);

    int blocks = (E + 255) / 256;
    edge_fused_kernel<<<blocks, 256>>>(h, pos, ei, Wrbf, E);
    node_kernel<<<(N + 31) / 32, 128>>>(h, Wout, Wsgp, out, N);
}